// round 7
// baseline (speedup 1.0000x reference)
#include <cuda_runtime.h>
#include <cuda_bf16.h>
#include <math.h>

#define CELLN 14
#define NCLS  80
#define BPC   3
#define FEAT  95            // 80 + 3 + 12
#define CELLS2 196          // 14*14
#define PRED_PER_B 18620    // 196*95
#define CSF   32.0f
#define IMGF  448.0f
#define EPSF  1e-9f
#define INV_PI2_4 0.40528473456935109f   // 4/pi^2
#define MAXB  2048
#define MAXM  32

__device__ unsigned g_cover[MAXB * CELLS2];      // per-cell object coverage bits
__device__ unsigned g_cmask[MAXB * CELLS2];      // per-cell center bits
__device__ float2   g_stats[MAXB * CELLS2];      // per-cell {class sumsq, conf sumsq}
__device__ float    g_pk[MAXB * MAXM];           // per-(b,o) sum of p_k over mask
__device__ int      g_kcls[MAXB * MAXM];         // per-(b,o) class id
__device__ float    g_conf[MAXB];                // per-batch conf sumsq
__device__ float    g_center[MAXB * MAXM * 16];  // per-(b,o) center-cell feats 80..94
__device__ float    g_obj_loss[MAXB * MAXM];
__device__ int      g_count = 0;

// ---------------------------------------------------------------------------
// K0: zero scratch (graph-replay safe).
// ---------------------------------------------------------------------------
__global__ void zero_kernel(int ncells, int npairs, int B)
{
    const int i = blockIdx.x * 256 + threadIdx.x;
    const int stride = gridDim.x * 256;
    for (int t = i; t < ncells; t += stride) { g_cover[t] = 0u; g_cmask[t] = 0u; }
    for (int t = i; t < npairs; t += stride) g_pk[t] = 0.0f;
    for (int t = i; t < B;      t += stride) g_conf[t] = 0.0f;
}

// ---------------------------------------------------------------------------
// K0b: warp per (batch,object): coverage / center bitmasks + class id.
// ---------------------------------------------------------------------------
__global__ __launch_bounds__(256)
void setup_kernel(const float* __restrict__ labels,
                  const int* __restrict__ objects_num, int B, int M)
{
    const int g    = (blockIdx.x * 256 + threadIdx.x) >> 5;
    const int lane = threadIdx.x & 31;
    if (g >= B * M) return;
    const int b = g / M;
    const int o = g - b * M;

    int nobj = objects_num[b];
    if (nobj > M) nobj = M;
    if (nobj > MAXM) nobj = MAXM;
    if (o >= nobj) return;

    const float* lb = labels + (size_t)g * 5;
    const float x = lb[0], y = lb[1], w = lb[2], h = lb[3];

    int ix0 = (int)floorf((x - 0.5f * w) * (1.0f / CSF));
    int ix1 = (int)fminf(ceilf((x + 0.5f * w) * (1.0f / CSF)), (float)CELLN);
    int iy0 = (int)floorf((y - 0.5f * h) * (1.0f / CSF));
    int iy1 = (int)fminf(ceilf((y + 0.5f * h) * (1.0f / CSF)), (float)CELLN);
    ix0 = max(ix0, 0); iy0 = max(iy0, 0);
    const int nx = max(0, ix1 - ix0);
    const int ny = max(0, iy1 - iy0);
    const int cnt = nx * ny;

    for (int t = lane; t < cnt; t += 32) {
        const int iy = iy0 + t / nx;
        const int ix = ix0 + t % nx;
        atomicOr(&g_cover[b * CELLS2 + iy * CELLN + ix], 1u << o);
    }
    if (lane == 0) {
        const int cx = (int)floorf(x * (1.0f / CSF));
        const int cy = (int)floorf(y * (1.0f / CSF));
        atomicOr(&g_cmask[b * CELLS2 + cy * CELLN + cx], 1u << o);
        g_kcls[g] = (int)lb[4];
    }
}

// ---------------------------------------------------------------------------
// K1: warp per 2 cells — THE ONLY READER OF predicts. Stats + in-stream
// export of p_k sums (coverage bits) and center-cell tails.
// ---------------------------------------------------------------------------
__device__ __forceinline__ void export_cell(
    int cell, int M, float a, float bv, float q, int lane)
{
    const int bb = cell / CELLS2;
    unsigned cov = g_cover[cell];
    while (cov) {
        const int o = __ffs(cov) - 1; cov &= cov - 1;
        const int k = g_kcls[bb * M + o];
        const float va = __shfl_sync(0xFFFFFFFFu, a,  k & 31);
        const float vb = __shfl_sync(0xFFFFFFFFu, bv, k & 31);
        const float vq = __shfl_sync(0xFFFFFFFFu, q,  k & 31);
        const float pk = (k < 32) ? va : ((k < 64) ? vb : vq);
        if (lane == 0) atomicAdd(&g_pk[bb * M + o], pk);
    }
    unsigned cen = g_cmask[cell];
    while (cen) {
        const int o = __ffs(cen) - 1; cen &= cen - 1;
        if (lane >= 16 && lane < 31)
            g_center[(bb * M + o) * 16 + (lane - 16)] = q;
    }
}

__global__ __launch_bounds__(256)
void stats_kernel(const float* __restrict__ P, int ncells, int M)
{
    const int wg   = (blockIdx.x * 256 + threadIdx.x) >> 5;
    const int lane = threadIdx.x & 31;
    const int c0 = wg * 2;
    if (c0 >= ncells) return;
    const bool has1 = (c0 + 1) < ncells;

    const float* p0 = P + (size_t)c0 * FEAT;
    const float* p1 = p0 + FEAT;
    const float a0 = p0[lane], b0 = p0[lane + 32], q0 = (lane < 31) ? p0[lane + 64] : 0.0f;
    float a1 = 0.f, b1 = 0.f, q1 = 0.f;
    if (has1) { a1 = p1[lane]; b1 = p1[lane + 32]; q1 = (lane < 31) ? p1[lane + 64] : 0.0f; }

    float cls0 = a0 * a0 + b0 * b0;
    float cls1 = a1 * a1 + b1 * b1;
    float conf0 = 0.f, conf1 = 0.f;
    const float q02 = q0 * q0, q12 = q1 * q1;
    if (lane < 16)      { cls0 += q02;  cls1 += q12; }   // feat 64..79: class
    else if (lane < 19) { conf0 = q02;  conf1 = q12; }   // feat 80..82: confidence

    #pragma unroll
    for (int off = 16; off; off >>= 1) {
        cls0  += __shfl_xor_sync(0xFFFFFFFFu, cls0,  off);
        cls1  += __shfl_xor_sync(0xFFFFFFFFu, cls1,  off);
        conf0 += __shfl_xor_sync(0xFFFFFFFFu, conf0, off);
        conf1 += __shfl_xor_sync(0xFFFFFFFFu, conf1, off);
    }
    if (lane == 0) {
        g_stats[c0] = make_float2(cls0, conf0);
        atomicAdd(&g_conf[c0 / CELLS2], conf0);
        if (has1) {
            g_stats[c0 + 1] = make_float2(cls1, conf1);
            atomicAdd(&g_conf[(c0 + 1) / CELLS2], conf1);
        }
    }

    export_cell(c0, M, a0, b0, q0, lane);
    if (has1) export_cell(c0 + 1, M, a1, b1, q1, lane);
}

// ---------------------------------------------------------------------------
// K2: warp per (batch,object). Reads ONLY compact L2-hot arrays.
// ---------------------------------------------------------------------------
__global__ __launch_bounds__(256)
void obj_kernel(const float* __restrict__ labels,
                const int*   __restrict__ objects_num,
                float* __restrict__ out, int B, int M, int nblocks)
{
    __shared__ float sred[8];
    __shared__ int   s_last;

    const int tid  = threadIdx.x;
    const int lane = tid & 31;
    const int wid  = tid >> 5;
    const int g    = blockIdx.x * 8 + wid;
    const int nwork = B * M;

    if (g < nwork) {
        const int b = g / M;
        const int o = g - b * M;
        float loss = 0.0f;

        int nobj = objects_num[b];
        if (nobj > M) nobj = M;
        if (nobj > MAXM) nobj = MAXM;

        if (o < nobj) {
            const float* lb = labels + (size_t)g * 5;
            const float x = lb[0], y = lb[1], w = lb[2], h = lb[3];

            int ix0 = (int)floorf((x - 0.5f * w) * (1.0f / CSF));
            int ix1 = (int)fminf(ceilf((x + 0.5f * w) * (1.0f / CSF)), (float)CELLN);
            int iy0 = (int)floorf((y - 0.5f * h) * (1.0f / CSF));
            int iy1 = (int)fminf(ceilf((y + 0.5f * h) * (1.0f / CSF)), (float)CELLN);
            ix0 = max(ix0, 0); iy0 = max(iy0, 0);
            const int nx = max(0, ix1 - ix0);
            const int ny = max(0, iy1 - iy0);
            const int cnt = nx * ny;

            const float2* st = g_stats + b * CELLS2;

            // class loss: sum over mask of (sumsq + 1) - 2 * pk_sum
            float cls = 0.0f;
            for (int t = lane; t < cnt; t += 32) {
                const int iy = iy0 + t / nx;
                const int ix = ix0 + t % nx;
                cls += __ldg(&st[iy * CELLN + ix].x) + 1.0f;
            }
            #pragma unroll
            for (int off = 16; off; off >>= 1)
                cls += __shfl_xor_sync(0xFFFFFFFFu, cls, off);
            cls -= 2.0f * __ldg(&g_pk[g]);

            const float cs = __ldg(&g_conf[b]);

            const int cx = (int)floorf(x * (1.0f / CSF));
            const int cy = (int)floorf(y * (1.0f / CSF));
            const float* sc = g_center + (size_t)g * 16;

            float ciou = -1e30f;
            float pC = 0.f, px = 0.f, py = 0.f, pw = 0.f, ph = 0.f;
            if (lane < BPC) {
                pC = __ldg(sc + lane);                       // feats 80..82
                const float* bx = sc + BPC + 4 * lane;       // feats 83..94
                px = __ldg(bx + 0) * CSF + (float)cx * CSF;
                py = __ldg(bx + 1) * CSF + (float)cy * CSF;
                pw = __ldg(bx + 2) * IMGF;
                ph = __ldg(bx + 3) * IMGF;

                // CIoU exactly per reference (incl. centers-vs-widths enclose quirk)
                const float x11 = px - 0.5f * pw, x12 = px + 0.5f * pw;
                const float y11 = py - 0.5f * ph, y12 = py + 0.5f * ph;
                const float x21 = x - 0.5f * w,   x22 = x + 0.5f * w;
                const float y21 = y - 0.5f * h,   y22 = y + 0.5f * h;
                const float iw = fmaxf(fminf(x12, x22) - fmaxf(x11, x21), 0.0f);
                const float ih = fmaxf(fminf(y12, y22) - fmaxf(y11, y21), 0.0f);
                const float inter = iw * ih;
                const float uni = pw * ph + w * h - inter;
                const float iou = inter / (uni + EPSF);
                const float cd  = (px - x) * (px - x) + (py - y) * (py - y);
                const float el = fminf(px, x), er = fmaxf(pw, w);
                const float et = fminf(py, y), eb = fmaxf(ph, h);
                const float ed = (er - el) * (er - el) + (eb - et) * (eb - et);
                const float da = atanf(w / (h + EPSF)) - atanf(pw / (ph + EPSF));
                const float v  = INV_PI2_4 * da * da;
                const float alpha = v / (1.0f - iou + v + EPSF);
                ciou = iou - cd / (ed + EPSF) - alpha * v;
            }
            float m = ciou;
            m = fmaxf(m, __shfl_xor_sync(0xFFFFFFFFu, m, 1));
            m = fmaxf(m, __shfl_xor_sync(0xFFFFFFFFu, m, 2));

            float contrib = 0.0f;
            if (lane < BPC && ciou >= m) {
                const float d = pC - ciou;
                contrib += 0.5f * d * d;           // object loss
                contrib -= 0.25f * pC * pC;        // removed from noobject term
                const float dx = (px - x) * (1.0f / CSF);
                const float dy = (py - y) * (1.0f / CSF);
                const float swp = sqrtf(fminf(fmaxf(pw, 0.0f), IMGF));
                const float shp = sqrtf(fminf(fmaxf(ph, 0.0f), IMGF));
                const float dw = swp - sqrtf(fabsf(w));
                const float dh = shp - sqrtf(fabsf(h));
                contrib += 5.0f * (0.5f * dx * dx + 0.5f * dy * dy
                                   + (0.5f * dw * dw) * (1.0f / IMGF)
                                   + (0.5f * dh * dh) * (1.0f / IMGF));
            }
            contrib += __shfl_xor_sync(0xFFFFFFFFu, contrib, 1);
            contrib += __shfl_xor_sync(0xFFFFFFFFu, contrib, 2);

            loss = 0.5f * cls + contrib + 0.25f * cs;
        }
        if (lane == 0) g_obj_loss[g] = loss;
    }

    // ---- last-finished block: deterministic-order final reduction ----
    __syncthreads();
    if (tid == 0) {
        __threadfence();
        int prev = atomicAdd(&g_count, 1);
        s_last = (prev == nblocks - 1);
    }
    __syncthreads();
    if (s_last) {
        float a = 0.0f;
        for (int i = tid; i < nwork; i += 256) a += g_obj_loss[i];
        #pragma unroll
        for (int off = 16; off; off >>= 1)
            a += __shfl_xor_sync(0xFFFFFFFFu, a, off);
        if (lane == 0) sred[wid] = a;
        __syncthreads();
        if (tid == 0) {
            float s = 0.0f;
            #pragma unroll
            for (int i = 0; i < 8; i++) s += sred[i];
            out[0] = s / (float)B;
            g_count = 0;           // reset for next graph replay
        }
    }
}

extern "C" void kernel_launch(void* const* d_in, const int* in_sizes, int n_in,
                              void* d_out, int out_size)
{
    const float* predicts = (const float*)d_in[0];
    const float* labels   = (const float*)d_in[1];
    const int*   objnum   = (const int*)d_in[2];
    float* out = (float*)d_out;

    const int B = in_sizes[2];
    const int M = in_sizes[1] / (B * 5);
    const int ncells = B * CELLS2;
    const int npairs = B * M;

    const int grid0 = (ncells + 255) / 256;
    const int gridS = (npairs + 7) / 8;
    const int grid1 = ((ncells + 1) / 2 + 7) / 8;
    const int grid2 = (npairs + 7) / 8;

    zero_kernel <<<grid0, 256>>>(ncells, npairs, B);
    setup_kernel<<<gridS, 256>>>(labels, objnum, B, M);
    stats_kernel<<<grid1, 256>>>(predicts, ncells, M);
    obj_kernel  <<<grid2, 256>>>(labels, objnum, out, B, M, grid2);
}

// round 8
// speedup vs baseline: 1.9245x; 1.9245x over previous
#include <cuda_runtime.h>
#include <cuda_bf16.h>
#include <math.h>

#define CELLN 14
#define NCLS  80
#define BPC   3
#define FEAT  95            // 80 + 3 + 12
#define CELLS2 196          // 14*14
#define PRED_PER_B 18620    // 196*95
#define CSF   32.0f
#define IMGF  448.0f
#define EPSF  1e-9f
#define INV_PI2_4 0.40528473456935109f   // 4/pi^2
#define MAXB  4096
#define MAXOBJ 32

__device__ float2 g_stats[MAXB * CELLS2];   // per (batch,cell): {class sumsq, conf sumsq}
__device__ int    g_arrive[MAXB];           // per-batch row-arrival counters (self-resetting)
__device__ float  g_batch_loss[MAXB];
__device__ int    g_count = 0;              // final-reduction counter (self-resetting)

// ---------------------------------------------------------------------------
// One block per (batch, row): 7 warps x 2 cells = 14 cells, trip count 1.
// Pure stream (proven 5.6 TB/s shape). The 14th-arriving row block of a batch
// runs that batch's per-object phase inline (L2-hot data, overlapped with the
// remaining batches' streaming). Last of B batches does the final reduction.
// ---------------------------------------------------------------------------
__global__ __launch_bounds__(224)
void yolo_kernel(const float* __restrict__ predicts,
                 const float* __restrict__ labels,
                 const int*   __restrict__ objects_num,
                 float* __restrict__ out, int B, int M)
{
    __shared__ float2 sst[CELLS2];
    __shared__ float  slab[MAXOBJ * 5];
    __shared__ float  sred[7];
    __shared__ float  sS;
    __shared__ int    s_do;

    const int blk  = blockIdx.x;
    const int b    = blk / CELLN;
    const int row  = blk - b * CELLN;
    const int tid  = threadIdx.x;
    const int lane = tid & 31;
    const int wid  = tid >> 5;          // 0..6

    // ---- stream: 2 cells per warp, front-batched loads ----
    const int cell0 = b * CELLS2 + row * CELLN + wid * 2;
    {
        const float* p0 = predicts + (size_t)cell0 * FEAT;
        const float* p1 = p0 + FEAT;
        const float a0 = p0[lane], b0 = p0[lane + 32], q0 = (lane < 31) ? p0[lane + 64] : 0.0f;
        const float a1 = p1[lane], b1 = p1[lane + 32], q1 = (lane < 31) ? p1[lane + 64] : 0.0f;

        float cls0 = a0 * a0 + b0 * b0;
        float cls1 = a1 * a1 + b1 * b1;
        float conf0 = 0.f, conf1 = 0.f;
        const float q02 = q0 * q0, q12 = q1 * q1;
        if (lane < 16)      { cls0 += q02;  cls1 += q12; }   // feats 64..79: class
        else if (lane < 19) { conf0 = q02;  conf1 = q12; }   // feats 80..82: confidence

        #pragma unroll
        for (int off = 16; off; off >>= 1) {
            cls0  += __shfl_xor_sync(0xFFFFFFFFu, cls0,  off);
            cls1  += __shfl_xor_sync(0xFFFFFFFFu, cls1,  off);
            conf0 += __shfl_xor_sync(0xFFFFFFFFu, conf0, off);
            conf1 += __shfl_xor_sync(0xFFFFFFFFu, conf1, off);
        }
        if (lane == 0) {
            g_stats[cell0]     = make_float2(cls0, conf0);
            g_stats[cell0 + 1] = make_float2(cls1, conf1);
        }
    }

    // publish + arrival
    __threadfence();
    __syncthreads();
    if (tid == 0) {
        const int prev = atomicAdd(&g_arrive[b], 1);
        s_do = (prev == CELLN - 1);
        if (prev == CELLN - 1) g_arrive[b] = 0;    // reset for next replay
    }
    __syncthreads();
    if (!s_do) return;
    __threadfence();                               // acquire side

    // ---- phase 2 (one block per batch) ----
    int nobj = objects_num[b];
    if (nobj > M) nobj = M;
    if (nobj > MAXOBJ) nobj = MAXOBJ;

    for (int i = tid; i < CELLS2; i += 224) sst[i] = g_stats[b * CELLS2 + i];
    for (int i = tid; i < nobj * 5; i += 224) slab[i] = labels[(size_t)b * M * 5 + i];
    __syncthreads();

    // batch confidence sum-of-squares
    float cs = 0.0f;
    for (int i = tid; i < CELLS2; i += 224) cs += sst[i].y;
    #pragma unroll
    for (int off = 16; off; off >>= 1) cs += __shfl_xor_sync(0xFFFFFFFFu, cs, off);
    if (lane == 0) sred[wid] = cs;
    __syncthreads();
    if (tid == 0) {
        float s = 0.0f;
        #pragma unroll
        for (int i = 0; i < 7; i++) s += sred[i];
        sS = s;
    }
    __syncthreads();
    const float S_conf2 = sS;
    __syncthreads();            // sred reused below

    const float* pb = predicts + (size_t)b * PRED_PER_B;

    float wacc = 0.0f;
    for (int o = wid; o < nobj; o += 7) {
        const float x = slab[o * 5 + 0], y = slab[o * 5 + 1];
        const float w = slab[o * 5 + 2], h = slab[o * 5 + 3];
        const int   k = (int)slab[o * 5 + 4];

        int ix0 = (int)floorf((x - 0.5f * w) * (1.0f / CSF));
        int ix1 = (int)fminf(ceilf((x + 0.5f * w) * (1.0f / CSF)), (float)CELLN);
        int iy0 = (int)floorf((y - 0.5f * h) * (1.0f / CSF));
        int iy1 = (int)fminf(ceilf((y + 0.5f * h) * (1.0f / CSF)), (float)CELLN);
        ix0 = max(ix0, 0); iy0 = max(iy0, 0);
        const int nx = max(0, ix1 - ix0);
        const int ny = max(0, iy1 - iy0);
        const int cnt = nx * ny;

        // class loss over masked cells: sumsq - 2 p_k + 1 (p_k gather: L2-hot)
        float cls = 0.0f;
        for (int t = lane; t < cnt; t += 32) {
            const int iy = iy0 + t / nx;
            const int ix = ix0 + t % nx;
            const int cell = iy * CELLN + ix;
            cls += sst[cell].x - 2.0f * __ldg(pb + cell * FEAT + k) + 1.0f;
        }
        #pragma unroll
        for (int off = 16; off; off >>= 1)
            cls += __shfl_xor_sync(0xFFFFFFFFu, cls, off);

        // center cell (read from predicts: L2-hot)
        const int cx = (int)floorf(x * (1.0f / CSF));
        const int cy = (int)floorf(y * (1.0f / CSF));
        const float* pc = pb + (cy * CELLN + cx) * FEAT;

        float ciou = -1e30f;
        float pC = 0.f, px = 0.f, py = 0.f, pw = 0.f, ph = 0.f;
        if (lane < BPC) {
            pC = __ldg(pc + NCLS + lane);
            const float* bx = pc + NCLS + BPC + 4 * lane;
            px = __ldg(bx + 0) * CSF + (float)cx * CSF;
            py = __ldg(bx + 1) * CSF + (float)cy * CSF;
            pw = __ldg(bx + 2) * IMGF;
            ph = __ldg(bx + 3) * IMGF;

            // CIoU exactly per reference (incl. centers-vs-widths enclose quirk)
            const float x11 = px - 0.5f * pw, x12 = px + 0.5f * pw;
            const float y11 = py - 0.5f * ph, y12 = py + 0.5f * ph;
            const float x21 = x - 0.5f * w,   x22 = x + 0.5f * w;
            const float y21 = y - 0.5f * h,   y22 = y + 0.5f * h;
            const float iw = fmaxf(fminf(x12, x22) - fmaxf(x11, x21), 0.0f);
            const float ih = fmaxf(fminf(y12, y22) - fmaxf(y11, y21), 0.0f);
            const float inter = iw * ih;
            const float uni = pw * ph + w * h - inter;
            const float iou = inter / (uni + EPSF);
            const float cd  = (px - x) * (px - x) + (py - y) * (py - y);
            const float el = fminf(px, x), er = fmaxf(pw, w);
            const float et = fminf(py, y), eb = fmaxf(ph, h);
            const float ed = (er - el) * (er - el) + (eb - et) * (eb - et);
            const float da = atanf(w / (h + EPSF)) - atanf(pw / (ph + EPSF));
            const float v  = INV_PI2_4 * da * da;
            const float alpha = v / (1.0f - iou + v + EPSF);
            ciou = iou - cd / (ed + EPSF) - alpha * v;
        }
        float m = ciou;
        m = fmaxf(m, __shfl_xor_sync(0xFFFFFFFFu, m, 1));
        m = fmaxf(m, __shfl_xor_sync(0xFFFFFFFFu, m, 2));

        float contrib = 0.0f;
        if (lane < BPC && ciou >= m) {
            const float d = pC - ciou;
            contrib += 0.5f * d * d;           // object loss
            contrib -= 0.25f * pC * pC;        // removed from noobject term
            const float dx = (px - x) * (1.0f / CSF);
            const float dy = (py - y) * (1.0f / CSF);
            const float swp = sqrtf(fminf(fmaxf(pw, 0.0f), IMGF));
            const float shp = sqrtf(fminf(fmaxf(ph, 0.0f), IMGF));
            const float dw = swp - sqrtf(fabsf(w));
            const float dh = shp - sqrtf(fabsf(h));
            contrib += 5.0f * (0.5f * dx * dx + 0.5f * dy * dy
                               + (0.5f * dw * dw) * (1.0f / IMGF)
                               + (0.5f * dh * dh) * (1.0f / IMGF));
        }
        contrib += __shfl_xor_sync(0xFFFFFFFFu, contrib, 1);
        contrib += __shfl_xor_sync(0xFFFFFFFFu, contrib, 2);

        if (lane == 0)
            wacc += 0.5f * cls + contrib + 0.25f * S_conf2;
    }

    if (lane == 0) sred[wid] = wacc;
    __syncthreads();
    if (tid == 0) {
        float s = 0.0f;
        #pragma unroll
        for (int i = 0; i < 7; i++) s += sred[i];
        g_batch_loss[b] = s;
    }

    // ---- final reduction: last finished batch-block, deterministic order ----
    __threadfence();
    __syncthreads();
    if (tid == 0) {
        const int prev = atomicAdd(&g_count, 1);
        s_do = (prev == B - 1);
    }
    __syncthreads();
    if (!s_do) return;
    __threadfence();

    float a = 0.0f;
    for (int i = tid; i < B; i += 224) a += g_batch_loss[i];
    #pragma unroll
    for (int off = 16; off; off >>= 1)
        a += __shfl_xor_sync(0xFFFFFFFFu, a, off);
    if (lane == 0) sred[wid] = a;
    __syncthreads();
    if (tid == 0) {
        float s = 0.0f;
        #pragma unroll
        for (int i = 0; i < 7; i++) s += sred[i];
        out[0] = s / (float)B;
        g_count = 0;               // reset for next replay
    }
}

extern "C" void kernel_launch(void* const* d_in, const int* in_sizes, int n_in,
                              void* d_out, int out_size)
{
    const float* predicts = (const float*)d_in[0];
    const float* labels   = (const float*)d_in[1];
    const int*   objnum   = (const int*)d_in[2];
    float* out = (float*)d_out;

    const int B = in_sizes[2];
    const int M = in_sizes[1] / (B * 5);

    yolo_kernel<<<B * CELLN, 224>>>(predicts, labels, objnum, out, B, M);
}